// round 16
// baseline (speedup 1.0000x reference)
#include <cuda_runtime.h>
#include <cuda_fp16.h>
#include <cstdint>
#include <math.h>

// ---------------------------------------------------------------------------
// CrossAttention B=8, T=S=2048, D=1024 (single head).
// R15: all GEMMs 1-product fp16, CTA 128x128 with 256 threads (8 warps, 4x2,
// warp tile 32x64), 3x32KB stages, __launch_bounds__(256,2) for 2 CTAs/SM so
// barrier + slice-start latency of one CTA hides under the other's MMAs.
// ---------------------------------------------------------------------------

#define EMBED 1024
#define BATCH 8
#define SEQ   2048
#define MTOT  (BATCH * SEQ)

typedef __half h16;

__device__ float g_Sc[(long long)BATCH * SEQ * SEQ];
__device__ h16 g_Thi[MTOT * EMBED];
__device__ h16 g_Shi[MTOT * EMBED];
__device__ h16 g_Wqhi[EMBED * EMBED];
__device__ h16 g_Wkhi[EMBED * EMBED];
__device__ h16 g_Wvhi[EMBED * EMBED];
__device__ h16 g_Wohi[EMBED * EMBED];
__device__ h16 g_Qhi[MTOT * EMBED];
__device__ h16 g_Khi[MTOT * EMBED];
__device__ h16 g_Vthi[MTOT * EMBED];                        // [B][D][S]
__device__ h16 g_Phi[(long long)BATCH * SEQ * SEQ];
__device__ h16 g_Chi[MTOT * EMBED];

__device__ __forceinline__ uint32_t smem_u32(const void* p) {
    uint32_t a;
    asm("{ .reg .u64 t; cvta.to.shared.u64 t, %1; cvt.u32.u64 %0, t; }" : "=r"(a) : "l"(p));
    return a;
}

#define LDSM4(r, addr) \
    asm volatile("ldmatrix.sync.aligned.m8n8.x4.shared.b16 {%0,%1,%2,%3}, [%4];" \
        : "=r"((r)[0]), "=r"((r)[1]), "=r"((r)[2]), "=r"((r)[3]) : "r"(addr))

#define MMA(d, a, b) \
    asm volatile("mma.sync.aligned.m16n8k16.row.col.f32.f16.f16.f32 " \
        "{%0,%1,%2,%3}, {%4,%5,%6,%7}, {%8,%9}, {%0,%1,%2,%3};" \
        : "+f"((d)[0]), "+f"((d)[1]), "+f"((d)[2]), "+f"((d)[3]) \
        : "r"((a)[0]), "r"((a)[1]), "r"((a)[2]), "r"((a)[3]), "r"((b)[0]), "r"((b)[1]))

#define CP16(dst, src) \
    asm volatile("cp.async.cg.shared.global [%0], [%1], 16;" :: "r"(dst), "l"(src))
#define CP_COMMIT() asm volatile("cp.async.commit_group;" ::: "memory")
#define CP_WAIT1()  asm volatile("cp.async.wait_group 1;" ::: "memory")

__device__ __forceinline__ uint32_t cvt2h(float f0, float f1) {
    uint32_t h;
    asm("cvt.rn.f16x2.f32 %0, %1, %2;" : "=r"(h) : "f"(f1), "f"(f0));
    return h;
}

// Stage 32 KB: A[0,16K) B[16K,32K). 128B rows (K64), swizzle chunk ^= row&7.
// EPI: 0=fp32, 2=hi fp16, 3=hi fp16 transposed [B][D][S]
#define STG    32768
#define SMEMB  (3 * STG)

template <int HAS_BIAS, int EPI>
__global__ __launch_bounds__(256, 2)
void mm_g(const h16* __restrict__ A, const h16* __restrict__ B,
          const float* __restrict__ bias,
          float* __restrict__ Cf, h16* __restrict__ Chi,
          int M, int N, int K,
          long long sA, long long sB, long long sC, float alpha)
{
    extern __shared__ char sm[];
    const uint32_t sb = smem_u32(sm);
    const int tid  = threadIdx.x;
    const int lane = tid & 31;
    const int wid  = tid >> 5;
    const int wm   = wid >> 1;   // 0..3, 32 rows each
    const int wn   = wid & 1;    // 0..1, 64 cols each

    const long long aoff = blockIdx.z * sA + (long long)(blockIdx.y * 128) * K;
    const long long boff = blockIdx.z * sB + (long long)(blockIdx.x * 128) * K;

    // loader: thread -> one row (A for tid<128, B else), 8 chunks of 16B
    const bool isB = tid >= 128;
    const int lrow = tid & 127;
    const int swr  = lrow & 7;
    const h16* prow = (isB ? B + boff : A + aoff) + (long long)lrow * K;
    const uint32_t dbase = (isB ? 16384u : 0u) + lrow * 128;

    auto load_stage = [&](int kofs, int st) {
        const uint32_t stb = sb + st * STG;
#pragma unroll
        for (int j = 0; j < 8; j++)
            CP16(stb + dbase + ((j ^ swr) << 4), prow + kofs + 8 * j);
    };

    const int g      = lane >> 3;
    const int rr     = lane & 7;
    const int rowoff = ((g & 1) << 3) + rr;
    const int csel   = g >> 1;
    const int sw     = rowoff & 7;
    uint32_t aRowB[2], bRowB[4];
#pragma unroll
    for (int mt = 0; mt < 2; mt++) aRowB[mt] = (wm * 32 + mt * 16 + rowoff) * 128;
#pragma unroll
    for (int pr = 0; pr < 4; pr++) bRowB[pr] = 16384u + (wn * 64 + pr * 16 + rowoff) * 128;

    float cacc[2][8][4];
#pragma unroll
    for (int i = 0; i < 2; i++)
#pragma unroll
        for (int j = 0; j < 8; j++)
#pragma unroll
            for (int q = 0; q < 4; q++) cacc[i][j][q] = 0.0f;

    // slice: interleave B LDSM with its consuming MMAs
    auto slice = [&](uint32_t stb, int s) {
        const uint32_t ck = (uint32_t)((((s << 1) + csel) ^ sw) << 4);
        uint32_t ah[2][4];
#pragma unroll
        for (int mt = 0; mt < 2; mt++) LDSM4(ah[mt], stb + aRowB[mt] + ck);
#pragma unroll
        for (int pr = 0; pr < 4; pr++) {
            uint32_t t[4];
            LDSM4(t, stb + bRowB[pr] + ck);
            uint32_t b0[2] = { t[0], t[2] };
            uint32_t b1[2] = { t[1], t[3] };
#pragma unroll
            for (int mt = 0; mt < 2; mt++) {
                MMA(cacc[mt][2 * pr],     ah[mt], b0);
                MMA(cacc[mt][2 * pr + 1], ah[mt], b1);
            }
        }
    };

    const int NSt = K >> 6;
    load_stage(0, 0);  CP_COMMIT();
    load_stage(64, 1); CP_COMMIT();
    CP_WAIT1();
    __syncthreads();

    for (int c = 0; c < NSt; c++) {
        const uint32_t stb = sb + (c % 3) * STG;
#pragma unroll
        for (int s = 0; s < 4; s++) slice(stb, s);
        if (c + 2 < NSt) load_stage((c + 2) << 6, (c + 2) % 3);
        CP_COMMIT();
        if (c + 1 < NSt) { CP_WAIT1(); __syncthreads(); }
    }

    const int l4 = lane >> 2;
    const int l2 = (lane & 3) * 2;
#pragma unroll
    for (int mt = 0; mt < 2; mt++) {
        const int mg = blockIdx.y * 128 + wm * 32 + mt * 16 + l4;
#pragma unroll
        for (int nt = 0; nt < 8; nt++) {
            const int n = blockIdx.x * 128 + wn * 64 + nt * 8 + l2;
            float b0 = 0.f, b1 = 0.f;
            if (HAS_BIAS) { b0 = bias[n]; b1 = bias[n + 1]; }
            float f0 = cacc[mt][nt][0] * alpha + b0;
            float f1 = cacc[mt][nt][1] * alpha + b1;
            float f2 = cacc[mt][nt][2] * alpha + b0;
            float f3 = cacc[mt][nt][3] * alpha + b1;
            if (EPI == 0) {
                float* cb = Cf + blockIdx.z * sC;
                *(float2*)&cb[(long long)mg * N + n]       = make_float2(f0, f1);
                *(float2*)&cb[(long long)(mg + 8) * N + n] = make_float2(f2, f3);
            } else if (EPI == 2) {
                *(uint32_t*)&Chi[blockIdx.z * sC + (long long)mg * N + n]       = cvt2h(f0, f1);
                *(uint32_t*)&Chi[blockIdx.z * sC + (long long)(mg + 8) * N + n] = cvt2h(f2, f3);
            } else {
                const int b  = mg >> 11;
                const int s2 = mg & 2047;
                uint16_t* vh = (uint16_t*)(Chi + (long long)b * EMBED * SEQ + s2);
                uint32_t h = cvt2h(f0, f1);
                vh[(long long)n * SEQ]       = (uint16_t)(h & 0xFFFF);
                vh[(long long)(n + 1) * SEQ] = (uint16_t)(h >> 16);
                h = cvt2h(f2, f3);
                vh[(long long)n * SEQ + 8]       = (uint16_t)(h & 0xFFFF);
                vh[(long long)(n + 1) * SEQ + 8] = (uint16_t)(h >> 16);
            }
        }
    }
}

// ---------------------------------------------------------------------------
__global__ __launch_bounds__(256)
void softmax_kernel(const float* __restrict__ S, h16* __restrict__ Phi)
{
    const float* row = S + (long long)blockIdx.x * SEQ;
    const int t = threadIdx.x;
    const int lane = t & 31;
    const int wid  = t >> 5;

    float4 v0 = ((const float4*)row)[t];
    float4 v1 = ((const float4*)row)[t + 256];

    float m = fmaxf(fmaxf(fmaxf(v0.x, v0.y), fmaxf(v0.z, v0.w)),
                    fmaxf(fmaxf(v1.x, v1.y), fmaxf(v1.z, v1.w)));
#pragma unroll
    for (int o = 16; o > 0; o >>= 1)
        m = fmaxf(m, __shfl_xor_sync(0xFFFFFFFFu, m, o));

    __shared__ float red[8];
    if (lane == 0) red[wid] = m;
    __syncthreads();
    float M = red[0];
#pragma unroll
    for (int i = 1; i < 8; i++) M = fmaxf(M, red[i]);
    __syncthreads();

    v0.x = __expf(v0.x - M); v0.y = __expf(v0.y - M);
    v0.z = __expf(v0.z - M); v0.w = __expf(v0.w - M);
    v1.x = __expf(v1.x - M); v1.y = __expf(v1.y - M);
    v1.z = __expf(v1.z - M); v1.w = __expf(v1.w - M);

    float s = (v0.x + v0.y + v0.z + v0.w) + (v1.x + v1.y + v1.z + v1.w);
#pragma unroll
    for (int o = 16; o > 0; o >>= 1)
        s += __shfl_xor_sync(0xFFFFFFFFu, s, o);
    if (lane == 0) red[wid] = s;
    __syncthreads();
    float Ssum = 0.0f;
#pragma unroll
    for (int i = 0; i < 8; i++) Ssum += red[i];

    const float inv = 1.0f / Ssum;
    v0.x *= inv; v0.y *= inv; v0.z *= inv; v0.w *= inv;
    v1.x *= inv; v1.y *= inv; v1.z *= inv; v1.w *= inv;

    uint2* ph = (uint2*)(Phi + (long long)blockIdx.x * SEQ);
    ph[t]       = make_uint2(cvt2h(v0.x, v0.y), cvt2h(v0.z, v0.w));
    ph[t + 256] = make_uint2(cvt2h(v1.x, v1.y), cvt2h(v1.z, v1.w));
}

// fp32 -> fp16
__global__ __launch_bounds__(256)
void cvth_kernel(const float* __restrict__ src, h16* __restrict__ hi, int n4)
{
    int i = blockIdx.x * blockDim.x + threadIdx.x;
    if (i >= n4) return;
    float4 v = ((const float4*)src)[i];
    ((uint2*)hi)[i] = make_uint2(cvt2h(v.x, v.y), cvt2h(v.z, v.w));
}

extern "C" void kernel_launch(void* const* d_in, const int* in_sizes, int n_in,
                              void* d_out, int out_size)
{
    const float* target = (const float*)d_in[0];
    const float* source = (const float*)d_in[1];
    const float* Wq     = (const float*)d_in[2];
    const float* bq     = (const float*)d_in[3];
    const float* Wk     = (const float*)d_in[4];
    const float* bk     = (const float*)d_in[5];
    const float* Wv     = (const float*)d_in[6];
    const float* bv     = (const float*)d_in[7];
    const float* Wo     = (const float*)d_in[8];
    const float* bo     = (const float*)d_in[9];
    float* out = (float*)d_out;

    float* Sc;
    cudaGetSymbolAddress((void**)&Sc, g_Sc);
    h16 *Thi,*Shi,*Wqh,*Wkh,*Wvh,*Woh;
    h16 *Qhi,*Khi,*Vth,*Phi,*Chi;
    cudaGetSymbolAddress((void**)&Thi, g_Thi);
    cudaGetSymbolAddress((void**)&Shi, g_Shi);
    cudaGetSymbolAddress((void**)&Wqh, g_Wqhi);
    cudaGetSymbolAddress((void**)&Wkh, g_Wkhi);
    cudaGetSymbolAddress((void**)&Wvh, g_Wvhi);
    cudaGetSymbolAddress((void**)&Woh, g_Wohi);
    cudaGetSymbolAddress((void**)&Qhi, g_Qhi);
    cudaGetSymbolAddress((void**)&Khi, g_Khi);
    cudaGetSymbolAddress((void**)&Vth, g_Vthi);
    cudaGetSymbolAddress((void**)&Phi, g_Phi);
    cudaGetSymbolAddress((void**)&Chi, g_Chi);

    cudaFuncSetAttribute(mm_g<1, 2>, cudaFuncAttributeMaxDynamicSharedMemorySize, SMEMB);
    cudaFuncSetAttribute(mm_g<1, 3>, cudaFuncAttributeMaxDynamicSharedMemorySize, SMEMB);
    cudaFuncSetAttribute(mm_g<0, 0>, cudaFuncAttributeMaxDynamicSharedMemorySize, SMEMB);
    cudaFuncSetAttribute(mm_g<0, 2>, cudaFuncAttributeMaxDynamicSharedMemorySize, SMEMB);
    cudaFuncSetAttribute(mm_g<1, 0>, cudaFuncAttributeMaxDynamicSharedMemorySize, SMEMB);

    const int nIn  = MTOT * EMBED / 4;
    const int nW   = EMBED * EMBED / 4;
    cvth_kernel<<<(nIn + 255) / 256, 256>>>(target, Thi, nIn);
    cvth_kernel<<<(nIn + 255) / 256, 256>>>(source, Shi, nIn);
    cvth_kernel<<<(nW + 255) / 256, 256>>>(Wq, Wqh, nW);
    cvth_kernel<<<(nW + 255) / 256, 256>>>(Wk, Wkh, nW);
    cvth_kernel<<<(nW + 255) / 256, 256>>>(Wv, Wvh, nW);
    cvth_kernel<<<(nW + 255) / 256, 256>>>(Wo, Woh, nW);

    // Q/K/V projections
    dim3 gProj(EMBED / 128, MTOT / 128, 1);
    mm_g<1, 2><<<gProj, 256, SMEMB>>>(Thi, Wqh, bq, nullptr, Qhi,
                                      MTOT, EMBED, EMBED, 0, 0, 0, 1.0f);
    mm_g<1, 2><<<gProj, 256, SMEMB>>>(Shi, Wkh, bk, nullptr, Khi,
                                      MTOT, EMBED, EMBED, 0, 0, 0, 1.0f);
    mm_g<1, 3><<<gProj, 256, SMEMB>>>(Shi, Wvh, bv, nullptr, Vth,
                                      MTOT, EMBED, EMBED, 0, 0, 0, 1.0f);

    // scores = Qh Kh^T / 32
    dim3 gScore(SEQ / 128, SEQ / 128, BATCH);
    mm_g<0, 0><<<gScore, 256, SMEMB>>>(Qhi, Khi, nullptr, Sc, nullptr,
                                       SEQ, SEQ, EMBED,
                                       (long long)SEQ * EMBED, (long long)SEQ * EMBED,
                                       (long long)SEQ * SEQ, 0.03125f);

    softmax_kernel<<<BATCH * SEQ, 256>>>(Sc, Phi);

    // ctx = P Vh (hi fp16 out)
    dim3 gAV(EMBED / 128, SEQ / 128, BATCH);
    mm_g<0, 2><<<gAV, 256, SMEMB>>>(Phi, Vth, nullptr, nullptr, Chi,
                                    SEQ, EMBED, SEQ,
                                    (long long)SEQ * SEQ, (long long)EMBED * SEQ,
                                    (long long)SEQ * EMBED, 1.0f);

    // out = Ch @ Woh^T + bo (fp32 out)
    mm_g<1, 0><<<gProj, 256, SMEMB>>>(Chi, Woh, bo, out, nullptr,
                                      MTOT, EMBED, EMBED, 0, 0, 0, 1.0f);
}